// round 11
// baseline (speedup 1.0000x reference)
#include <cuda_runtime.h>
#include <cuda_bf16.h>
#include <cstdint>

// ---------------------------------------------------------------------------
// SkinDeformNet via warp-level mma.sync (sm_80+ baseline PTX, works on sm_103
// without the 'a' feature set).
//   T[128x16] = W[128x80]_bf16 @ B[80x16]_bf16   (2-term bf16 split, fp32 acc)
// K blocks: 0-23 w0*a0, 24-47 w0*a1, 48-71 w1*a0, 72-79 zero pad.
// Kernel A (rig): Rodrigues + chain -> Rs, Jt, A12 scratch, per-batch B image.
// Kernel B (pts): stage W panel (SW128), ldmatrix A-frags, LDS B-frags,
//                 20x mma.m16n8k16, epilogue via warp-local smem round-trip.
// ---------------------------------------------------------------------------

#define MAX_B 64
#define TILE  128

// A12: 12 floats (3x4) per joint per batch - scalar fixup path
__device__ __align__(16) float g_A[MAX_B * 24 * 12];
// B images: [batch][n=16][k=88] bf16 (stride 88 halves = 176 B) = 2816 B/batch
__device__ __align__(16) unsigned int g_Bt[MAX_B * 704];

__device__ const int c_par[24]   = {-1,0,0,0,1,2,3,4,5,6,7,8,9,9,9,12,13,14,16,17,18,19,20,21};
__device__ const int c_depth[24] = { 0,1,1,1,2,2,2,3,3,3,4,4,4,4,4, 5, 5, 5, 6, 6, 7, 7, 8, 8};

static __device__ __forceinline__ unsigned int packbf(float a, float b) {
    __nv_bfloat16 ha = __float2bfloat16_rn(a), hb = __float2bfloat16_rn(b);
    unsigned short ua = *(unsigned short*)&ha, ub = *(unsigned short*)&hb;
    return (unsigned int)ua | ((unsigned int)ub << 16);
}

// ============================= Kernel A: rig ===============================
__global__ void rig_kernel(const float* __restrict__ Js,
                           const float* __restrict__ poses,
                           float* __restrict__ outRs,
                           float* __restrict__ outJt)
{
    const int b = blockIdx.x;
    const int j = threadIdx.x;      // 32 threads, j<24 active

    __shared__ float sJ[24][3];
    __shared__ float sRes[24][12];

    // zero this batch's B image (pads must be 0)
    for (int i = j; i < 704; i += 32) g_Bt[b * 704 + i] = 0u;

    float R[9];
    if (j < 24) {
        float rx = poses[b*72 + j*3 + 0];
        float ry = poses[b*72 + j*3 + 1];
        float rz = poses[b*72 + j*3 + 2];
        float ang = sqrtf(rx*rx + ry*ry + rz*rz) + 1e-8f;
        float inv = 1.0f / ang;
        float x = rx*inv, y = ry*inv, z = rz*inv;
        float s = sinf(ang), c = cosf(ang);
        float o = 1.0f - c;
        R[0] = 1.0f - o*(y*y + z*z);
        R[1] = -s*z + o*(x*y);
        R[2] =  s*y + o*(x*z);
        R[3] =  s*z + o*(x*y);
        R[4] = 1.0f - o*(x*x + z*z);
        R[5] = -s*x + o*(y*z);
        R[6] = -s*y + o*(x*z);
        R[7] =  s*x + o*(y*z);
        R[8] = 1.0f - o*(x*x + y*y);
        #pragma unroll
        for (int i = 0; i < 9; i++) outRs[b*216 + j*9 + i] = R[i];
        sJ[j][0] = Js[b*72 + j*3 + 0];
        sJ[j][1] = Js[b*72 + j*3 + 1];
        sJ[j][2] = Js[b*72 + j*3 + 2];
    }
    __syncthreads();

    float res[12];
    const int dj = (j < 24) ? c_depth[j] : -1;
    for (int lv = 0; lv < 9; lv++) {
        if (dj == lv) {
            if (j == 0) {
                res[0]=R[0]; res[1]=R[1]; res[2] =R[2]; res[3] =sJ[0][0];
                res[4]=R[3]; res[5]=R[4]; res[6] =R[5]; res[7] =sJ[0][1];
                res[8]=R[6]; res[9]=R[7]; res[10]=R[8]; res[11]=sJ[0][2];
            } else {
                int p = c_par[j];
                float tx = sJ[j][0]-sJ[p][0], ty = sJ[j][1]-sJ[p][1], tz = sJ[j][2]-sJ[p][2];
                #pragma unroll
                for (int r = 0; r < 3; r++) {
                    float p0 = sRes[p][r*4+0], p1 = sRes[p][r*4+1];
                    float p2 = sRes[p][r*4+2], p3 = sRes[p][r*4+3];
                    res[r*4+0] = p0*R[0] + p1*R[3] + p2*R[6];
                    res[r*4+1] = p0*R[1] + p1*R[4] + p2*R[7];
                    res[r*4+2] = p0*R[2] + p1*R[5] + p2*R[8];
                    res[r*4+3] = p0*tx   + p1*ty   + p2*tz + p3;
                }
            }
            #pragma unroll
            for (int i = 0; i < 12; i++) sRes[j][i] = res[i];
        }
        __syncthreads();
    }

    if (j < 24) {
        float Jx = sJ[j][0], Jy = sJ[j][1], Jz = sJ[j][2];
        float A12[12];
        #pragma unroll
        for (int r = 0; r < 3; r++) {
            A12[r*4+0] = res[r*4+0];
            A12[r*4+1] = res[r*4+1];
            A12[r*4+2] = res[r*4+2];
            A12[r*4+3] = res[r*4+3] - (res[r*4+0]*Jx + res[r*4+1]*Jy + res[r*4+2]*Jz);
            outJt[b*72 + j*3 + r] = res[r*4+3];
        }
        #pragma unroll
        for (int i = 0; i < 12; i++) g_A[(b*24 + j)*12 + i] = A12[i];
    }
    __syncthreads();   // zero-fill complete before scattered half writes

    if (j < 24) {
        // B image rows: k=j -> a0, k=24+j -> a1, k=48+j -> a0  (n-major, stride 88)
        __nv_bfloat16* Bt = (__nv_bfloat16*)g_Bt + b * 1408;
        const float* A12p = &g_A[(b*24 + j)*12];
        #pragma unroll
        for (int n = 0; n < 16; n++) {
            float v = (n < 12) ? A12p[n] : ((n == 15) ? 1.0f : 0.0f);
            __nv_bfloat16 a0 = __float2bfloat16_rn(v);
            float lo = v - __bfloat162float(a0);
            __nv_bfloat16 a1 = __float2bfloat16_rn(lo);
            Bt[n*88 + j]      = a0;
            Bt[n*88 + 24 + j] = a1;
            Bt[n*88 + 48 + j] = a0;
        }
    }
}

// ============================= Kernel B: points ============================
// Static smem: A0 panel 128 rows x 128B (SW128) | A1 panel 128 x 48B | B 16 x 176B
#define SMA0 0
#define SMA1 16384
#define SMB  22528
#define SMSZ 25344

static __device__ __forceinline__ void ldm_x4(uint32_t addr, uint32_t& r0, uint32_t& r1,
                                              uint32_t& r2, uint32_t& r3) {
    asm volatile("ldmatrix.sync.aligned.m8n8.x4.shared.b16 {%0,%1,%2,%3}, [%4];"
                 : "=r"(r0), "=r"(r1), "=r"(r2), "=r"(r3) : "r"(addr));
}
static __device__ __forceinline__ void mma_bf16(float* c, uint32_t a0, uint32_t a1,
                                                uint32_t a2, uint32_t a3,
                                                uint32_t b0, uint32_t b1) {
    asm volatile("mma.sync.aligned.m16n8k16.row.col.f32.bf16.bf16.f32 "
                 "{%0,%1,%2,%3}, {%4,%5,%6,%7}, {%8,%9}, {%0,%1,%2,%3};"
                 : "+f"(c[0]), "+f"(c[1]), "+f"(c[2]), "+f"(c[3])
                 : "r"(a0), "r"(a1), "r"(a2), "r"(a3), "r"(b0), "r"(b1));
}

__global__ void __launch_bounds__(TILE)
pts_kernel(const float* __restrict__ ps,
           const float* __restrict__ ws,
           const void*  __restrict__ batch_raw,
           float* __restrict__ outP,
           float* __restrict__ outT,
           int N)
{
    __shared__ __align__(1024) char sm[SMSZ];
    uint32_t smb;
    asm("{ .reg .u64 t; cvta.to.shared.u64 t, %1; cvt.u32.u64 %0, t; }"
        : "=r"(smb) : "l"(sm));

    const int tid  = threadIdx.x;
    const int lane = tid & 31;
    const int wid  = tid >> 5;
    const int base = blockIdx.x * TILE;
    const int n    = base + tid;
    const int nc   = (n < N) ? n : (N - 1);

    const int*       b32 = (const int*)batch_raw;
    const long long* b64 = (const long long*)batch_raw;

    // dtype probe: batch sorted, max = B-1 > 0; int64 -> last 32-bit word is 0.
    const bool is64 = (__ldg(b32 + (N - 1)) == 0);
    const int  b    = is64 ? (int)__ldg(b64 + nc)   : __ldg(b32 + nc);
    const int  blo  = is64 ? (int)__ldg(b64 + base) : __ldg(b32 + base);

    // prefetch streaming inputs
    const float px = __ldg(ps + (size_t)nc*3 + 0);
    const float py = __ldg(ps + (size_t)nc*3 + 1);
    const float pz = __ldg(ps + (size_t)nc*3 + 2);
    float w[24];
    {
        const float4* wsv = reinterpret_cast<const float4*>(ws + (size_t)nc * 24);
        #pragma unroll
        for (int i = 0; i < 6; i++) {
            float4 v = __ldg(wsv + i);
            w[i*4+0] = v.x; w[i*4+1] = v.y; w[i*4+2] = v.z; w[i*4+3] = v.w;
        }
    }

    // bf16 split: w0 = bf16(w), w1 = bf16(w - w0)
    unsigned int w0p[12], w1p[12];
    #pragma unroll
    for (int i = 0; i < 12; i++) {
        float a = w[2*i], c = w[2*i+1];
        __nv_bfloat16 ha = __float2bfloat16_rn(a), hc = __float2bfloat16_rn(c);
        float ra = a - __bfloat162float(ha);
        float rc = c - __bfloat162float(hc);
        unsigned short ua = *(unsigned short*)&ha, uc = *(unsigned short*)&hc;
        w0p[i] = (unsigned int)ua | ((unsigned int)uc << 16);
        w1p[i] = packbf(ra, rc);
    }

    // ---- stage A0 panel row tid: k0-23 w0 | k24-47 w0 | k48-63 w1[0..15] ----
    {
        const unsigned int swz = (unsigned)(tid & 7) * 16u;
        char* p = sm + SMA0;
        #pragma unroll
        for (int c = 0; c < 8; c++) {
            uint4 q;
            const int i0 = c * 4;   // uint index 0..31
            unsigned int u[4];
            #pragma unroll
            for (int e = 0; e < 4; e++) {
                int i = i0 + e;
                u[e] = (i < 12) ? w0p[i] : (i < 24) ? w0p[i-12] : w1p[i-24];
            }
            q.x = u[0]; q.y = u[1]; q.z = u[2]; q.w = u[3];
            unsigned int off = (unsigned)tid*128u + (unsigned)c*16u;
            *reinterpret_cast<uint4*>(p + (off ^ swz)) = q;
        }
        // ---- stage A1 panel row tid: k64-71 w1[16..23] | k72-79 zero ----
        char* p1 = sm + SMA1 + tid * 48;
        uint4 q0; q0.x = w1p[8]; q0.y = w1p[9]; q0.z = w1p[10]; q0.w = w1p[11];
        *reinterpret_cast<uint4*>(p1)      = q0;
        *reinterpret_cast<uint4*>(p1 + 16) = make_uint4(0u, 0u, 0u, 0u);
    }

    // ---- copy B image (2816 B = 176 uint4) ----
    {
        const uint4* src = reinterpret_cast<const uint4*>(g_Bt) + (size_t)blo * 176;
        uint4* dst = reinterpret_cast<uint4*>(sm + SMB);
        dst[tid] = __ldg(src + tid);
        if (tid < 48) dst[tid + 128] = __ldg(src + tid + 128);
    }
    __syncthreads();

    // ---- B fragments: bf[kt][nt][r], k = kt*16 + (lane%4)*2 + 8r, n = nt*8 + lane/4
    uint32_t bf[5][2][2];
    {
        const char* Bp = sm + SMB;
        const int kbase = (lane & 3) * 2;
        const int nrow  = lane >> 2;
        #pragma unroll
        for (int kt = 0; kt < 5; kt++)
            #pragma unroll
            for (int nt = 0; nt < 2; nt++)
                #pragma unroll
                for (int r = 0; r < 2; r++) {
                    int k = kt*16 + kbase + 8*r;
                    int nn = nt*8 + nrow;
                    bf[kt][nt][r] = *reinterpret_cast<const uint32_t*>(Bp + nn*176 + k*2);
                }
    }

    // ---- MMA mainloop: 2 m-tiles x 2 n-tiles x 5 k-steps ----
    float acc[2][2][4];
    #pragma unroll
    for (int mt = 0; mt < 2; mt++)
        #pragma unroll
        for (int nt = 0; nt < 2; nt++)
            #pragma unroll
            for (int e = 0; e < 4; e++) acc[mt][nt][e] = 0.0f;

    const int rowb = wid * 32;
    #pragma unroll
    for (int kt = 0; kt < 5; kt++) {
        #pragma unroll
        for (int mt = 0; mt < 2; mt++) {
            const unsigned int row = (unsigned)(rowb + mt*16 + (lane & 15));
            uint32_t addr;
            if (kt < 4) {
                unsigned int off = row*128u + (unsigned)kt*32u + (unsigned)(lane >> 4)*16u;
                addr = smb + SMA0 + (off ^ ((row & 7u)*16u));
            } else {
                addr = smb + SMA1 + row*48u + (unsigned)(lane >> 4)*16u;
            }
            uint32_t a0, a1, a2, a3;
            ldm_x4(addr, a0, a1, a2, a3);
            mma_bf16(acc[mt][0], a0, a1, a2, a3, bf[kt][0][0], bf[kt][0][1]);
            mma_bf16(acc[mt][1], a0, a1, a2, a3, bf[kt][1][0], bf[kt][1][1]);
        }
    }

    // ---- epilogue: frags -> warp-local sT (overlay own A0 rows), read own row
    __syncwarp();
    {
        char* p = sm + SMA0;
        #pragma unroll
        for (int mt = 0; mt < 2; mt++)
            #pragma unroll
            for (int nt = 0; nt < 2; nt++) {
                unsigned int r0 = (unsigned)(rowb + mt*16 + (lane >> 2));
                unsigned int r1 = r0 + 8;
                unsigned int cb = ((unsigned)nt*8u + (unsigned)(lane & 3)*2u) * 4u;
                float2 v0 = make_float2(acc[mt][nt][0], acc[mt][nt][1]);
                float2 v1 = make_float2(acc[mt][nt][2], acc[mt][nt][3]);
                *reinterpret_cast<float2*>(p + ((r0*128u + cb) ^ ((r0 & 7u)*16u))) = v0;
                *reinterpret_cast<float2*>(p + ((r1*128u + cb) ^ ((r1 & 7u)*16u))) = v1;
            }
    }
    __syncwarp();

    float tv[16];
    {
        const char* p = sm + SMA0;
        const unsigned int swz = (unsigned)(tid & 7) * 16u;
        #pragma unroll
        for (int c = 0; c < 4; c++) {
            float4 q = *reinterpret_cast<const float4*>(
                p + (((unsigned)tid*128u + (unsigned)c*16u) ^ swz));
            tv[c*4+0] = q.x; tv[c*4+1] = q.y; tv[c*4+2] = q.z; tv[c*4+3] = q.w;
        }
    }

    // scalar fixup for points whose batch != blo (rare boundary tiles)
    if (b != blo) {
        const float* Ab = g_A + (size_t)b * 288;
        float a12[12];
        #pragma unroll
        for (int i = 0; i < 12; i++) a12[i] = 0.0f;
        float sw = 0.0f;
        for (int k = 0; k < 24; k++) {
            float wk = w[k];
            sw += wk;
            #pragma unroll
            for (int i = 0; i < 12; i++) a12[i] += wk * __ldg(Ab + k*12 + i);
        }
        #pragma unroll
        for (int i = 0; i < 12; i++) tv[i] = a12[i];
        tv[12] = 0.0f; tv[13] = 0.0f; tv[14] = 0.0f; tv[15] = sw;
    }

    if (n < N) {
        float4* Tp = reinterpret_cast<float4*>(outT + (size_t)n * 16);
        Tp[0] = make_float4(tv[0],  tv[1],  tv[2],  tv[3]);
        Tp[1] = make_float4(tv[4],  tv[5],  tv[6],  tv[7]);
        Tp[2] = make_float4(tv[8],  tv[9],  tv[10], tv[11]);
        Tp[3] = make_float4(tv[12], tv[13], tv[14], tv[15]);

        outP[(size_t)n*3 + 0] = tv[0]*px + tv[1]*py + tv[2] *pz + tv[3];
        outP[(size_t)n*3 + 1] = tv[4]*px + tv[5]*py + tv[6] *pz + tv[7];
        outP[(size_t)n*3 + 2] = tv[8]*px + tv[9]*py + tv[10]*pz + tv[11];
    }
}

// =============================== launch ====================================
extern "C" void kernel_launch(void* const* d_in, const int* in_sizes, int n_in,
                              void* d_out, int out_size)
{
    const float* ps    = (const float*)d_in[0];
    const float* Js    = (const float*)d_in[1];
    const float* ws    = (const float*)d_in[2];
    const float* poses = (const float*)d_in[3];
    const void*  batch = d_in[4];

    const int N = in_sizes[0] / 3;
    int B = in_sizes[3] / 72;
    if (B > MAX_B) B = MAX_B;

    float* out   = (float*)d_out;
    float* outP  = out;                                  // N*3
    float* outT  = outP + (size_t)N * 3;                 // N*16
    float* outRs = outT + (size_t)N * 16;                // B*216
    float* outJt = outRs + (size_t)B * 216;              // B*72

    rig_kernel<<<B, 32>>>(Js, poses, outRs, outJt);

    const int blocks = (N + TILE - 1) / TILE;
    pts_kernel<<<blocks, TILE>>>(ps, ws, batch, outP, outT, N);
}

// round 12
// speedup vs baseline: 1.0413x; 1.0413x over previous
#include <cuda_runtime.h>
#include <cuda_bf16.h>
#include <cstdint>

// ---------------------------------------------------------------------------
// SkinDeformNet via warp-level mma.sync (sm_80 baseline PTX).
//   T[128x16] = W @ A16 with 3-term bf16 split: w0*a0 + w0*a1 + w1*a0.
// A panel (smem, SW128 128B rows): cols 0-23 w0 | pad | cols 32-55 w1 | pad.
// B fragments pre-generated in frag order by rig_kernel (2 images: a0, a1).
// w0 A-fragments are REUSED in registers for the w0*a1 term (no dup staging).
// W staged via fully coalesced float4 loads split in flight (no w registers).
// ---------------------------------------------------------------------------

#define MAX_B 64
#define TILE  128

// A12: 12 floats (3x4) per joint per batch - scalar fixup path
__device__ __align__(16) float g_A[MAX_B * 24 * 12];
// B frag images: [batch][img(2)][kt(2)][nt(2)][r(2)][lane(32)] = 512 words
__device__ __align__(16) unsigned int g_Bf[MAX_B * 512];

__device__ const int c_par[24]   = {-1,0,0,0,1,2,3,4,5,6,7,8,9,9,9,12,13,14,16,17,18,19,20,21};
__device__ const int c_depth[24] = { 0,1,1,1,2,2,2,3,3,3,4,4,4,4,4, 5, 5, 5, 6, 6, 7, 7, 8, 8};

// ============================= Kernel A: rig ===============================
__global__ void rig_kernel(const float* __restrict__ Js,
                           const float* __restrict__ poses,
                           float* __restrict__ outRs,
                           float* __restrict__ outJt)
{
    const int b = blockIdx.x;
    const int j = threadIdx.x;      // 32 threads, j<24 active

    __shared__ float sJ[24][3];
    __shared__ float sRes[24][12];
    __shared__ float sA16[24][16];

    float R[9];
    if (j < 24) {
        float rx = poses[b*72 + j*3 + 0];
        float ry = poses[b*72 + j*3 + 1];
        float rz = poses[b*72 + j*3 + 2];
        float ang = sqrtf(rx*rx + ry*ry + rz*rz) + 1e-8f;
        float inv = 1.0f / ang;
        float x = rx*inv, y = ry*inv, z = rz*inv;
        float s = sinf(ang), c = cosf(ang);
        float o = 1.0f - c;
        R[0] = 1.0f - o*(y*y + z*z);
        R[1] = -s*z + o*(x*y);
        R[2] =  s*y + o*(x*z);
        R[3] =  s*z + o*(x*y);
        R[4] = 1.0f - o*(x*x + z*z);
        R[5] = -s*x + o*(y*z);
        R[6] = -s*y + o*(x*z);
        R[7] =  s*x + o*(y*z);
        R[8] = 1.0f - o*(x*x + y*y);
        #pragma unroll
        for (int i = 0; i < 9; i++) outRs[b*216 + j*9 + i] = R[i];
        sJ[j][0] = Js[b*72 + j*3 + 0];
        sJ[j][1] = Js[b*72 + j*3 + 1];
        sJ[j][2] = Js[b*72 + j*3 + 2];
    }
    __syncthreads();

    float res[12];
    const int dj = (j < 24) ? c_depth[j] : -1;
    for (int lv = 0; lv < 9; lv++) {
        if (dj == lv) {
            if (j == 0) {
                res[0]=R[0]; res[1]=R[1]; res[2] =R[2]; res[3] =sJ[0][0];
                res[4]=R[3]; res[5]=R[4]; res[6] =R[5]; res[7] =sJ[0][1];
                res[8]=R[6]; res[9]=R[7]; res[10]=R[8]; res[11]=sJ[0][2];
            } else {
                int p = c_par[j];
                float tx = sJ[j][0]-sJ[p][0], ty = sJ[j][1]-sJ[p][1], tz = sJ[j][2]-sJ[p][2];
                #pragma unroll
                for (int r = 0; r < 3; r++) {
                    float p0 = sRes[p][r*4+0], p1 = sRes[p][r*4+1];
                    float p2 = sRes[p][r*4+2], p3 = sRes[p][r*4+3];
                    res[r*4+0] = p0*R[0] + p1*R[3] + p2*R[6];
                    res[r*4+1] = p0*R[1] + p1*R[4] + p2*R[7];
                    res[r*4+2] = p0*R[2] + p1*R[5] + p2*R[8];
                    res[r*4+3] = p0*tx   + p1*ty   + p2*tz + p3;
                }
            }
            #pragma unroll
            for (int i = 0; i < 12; i++) sRes[j][i] = res[i];
        }
        __syncthreads();
    }

    if (j < 24) {
        float Jx = sJ[j][0], Jy = sJ[j][1], Jz = sJ[j][2];
        float A12[12];
        #pragma unroll
        for (int r = 0; r < 3; r++) {
            A12[r*4+0] = res[r*4+0];
            A12[r*4+1] = res[r*4+1];
            A12[r*4+2] = res[r*4+2];
            A12[r*4+3] = res[r*4+3] - (res[r*4+0]*Jx + res[r*4+1]*Jy + res[r*4+2]*Jz);
            outJt[b*72 + j*3 + r] = res[r*4+3];
        }
        #pragma unroll
        for (int i = 0; i < 12; i++) {
            g_A[(b*24 + j)*12 + i] = A12[i];
            sA16[j][i] = A12[i];
        }
        sA16[j][12] = 0.0f; sA16[j][13] = 0.0f; sA16[j][14] = 0.0f; sA16[j][15] = 1.0f;
    }
    __syncthreads();

    // B fragment images in mma frag order:
    // word idx = ((img*2 + kt)*2 + nt)*2*32 + r*32 + lane
    // value = pack(Bimg[n][k], Bimg[n][k+1]); k = kt*16 + (lane&3)*2 + 8r;
    // n = nt*8 + lane/4. img 0 = a0 = bf16(v); img 1 = a1 = bf16(v - a0).
    for (int idx = j; idx < 512; idx += 32) {
        const int img = idx >> 8;
        const int rem = idx & 255;
        const int kt  = rem >> 7;
        const int nt  = (rem >> 6) & 1;
        const int r   = (rem >> 5) & 1;
        const int ln  = rem & 31;
        const int k   = kt*16 + (ln & 3)*2 + 8*r;
        const int nn  = nt*8 + (ln >> 2);

        unsigned short h[2];
        #pragma unroll
        for (int e = 0; e < 2; e++) {
            float v = (k + e < 24) ? sA16[k + e][nn] : 0.0f;
            __nv_bfloat16 a0 = __float2bfloat16_rn(v);
            if (img == 0) {
                h[e] = *(unsigned short*)&a0;
            } else {
                float lo = v - __bfloat162float(a0);
                __nv_bfloat16 a1 = __float2bfloat16_rn(lo);
                h[e] = *(unsigned short*)&a1;
            }
        }
        g_Bf[b*512 + idx] = (unsigned int)h[0] | ((unsigned int)h[1] << 16);
    }
}

// ============================= Kernel B: points ============================
// smem: A panel 128 rows x 128 B (SW128) | B frags 2048 B
#define SMA  0
#define SMBF 16384
#define SMSZ 18432

static __device__ __forceinline__ void ldm_x4(uint32_t addr, uint32_t& r0, uint32_t& r1,
                                              uint32_t& r2, uint32_t& r3) {
    asm volatile("ldmatrix.sync.aligned.m8n8.x4.shared.b16 {%0,%1,%2,%3}, [%4];"
                 : "=r"(r0), "=r"(r1), "=r"(r2), "=r"(r3) : "r"(addr));
}
static __device__ __forceinline__ void mma_bf16(float* c, const uint32_t* a,
                                                uint32_t b0, uint32_t b1) {
    asm volatile("mma.sync.aligned.m16n8k16.row.col.f32.bf16.bf16.f32 "
                 "{%0,%1,%2,%3}, {%4,%5,%6,%7}, {%8,%9}, {%0,%1,%2,%3};"
                 : "+f"(c[0]), "+f"(c[1]), "+f"(c[2]), "+f"(c[3])
                 : "r"(a[0]), "r"(a[1]), "r"(a[2]), "r"(a[3]), "r"(b0), "r"(b1));
}

__global__ void __launch_bounds__(TILE, 6)
pts_kernel(const float* __restrict__ ps,
           const float* __restrict__ ws,
           const void*  __restrict__ batch_raw,
           float* __restrict__ outP,
           float* __restrict__ outT,
           int N)
{
    __shared__ __align__(1024) char sm[SMSZ];
    uint32_t smb;
    asm("{ .reg .u64 t; cvta.to.shared.u64 t, %1; cvt.u32.u64 %0, t; }"
        : "=r"(smb) : "l"(sm));

    const int tid  = threadIdx.x;
    const int lane = tid & 31;
    const int wid  = tid >> 5;
    const int base = blockIdx.x * TILE;
    const int n    = base + tid;
    const int nc   = (n < N) ? n : (N - 1);

    const int*       b32 = (const int*)batch_raw;
    const long long* b64 = (const long long*)batch_raw;

    // dtype probe: batch sorted, max = B-1 > 0; int64 -> last 32-bit word is 0.
    const bool is64 = (__ldg(b32 + (N - 1)) == 0);
    const int  b    = is64 ? (int)__ldg(b64 + nc)   : __ldg(b32 + nc);
    const int  blo  = is64 ? (int)__ldg(b64 + base) : __ldg(b32 + base);

    // prefetch ps
    const float px = __ldg(ps + (size_t)nc*3 + 0);
    const float py = __ldg(ps + (size_t)nc*3 + 1);
    const float pz = __ldg(ps + (size_t)nc*3 + 2);

    // ---- zero the panel pads: bytes 48-63 and 112-127 of each row ----
    {
        #pragma unroll
        for (int q = tid; q < 256; q += TILE) {
            const unsigned int row = (unsigned)(q >> 1);
            const unsigned int cb  = 48u + (unsigned)(q & 1) * 64u;
            const unsigned int off = row*128u + (cb ^ ((row & 7u)*16u));
            *reinterpret_cast<uint4*>(sm + SMA + off) = make_uint4(0u,0u,0u,0u);
        }
    }

    // ---- coalesced W staging: linear float4 stream, split in flight ----
    // float4 i covers point row i/6, k-cols (i%6)*4 .. +3.
    // w0 -> bytes part*8, w1 -> bytes 64 + part*8 (swizzled).
    {
        const float4* wsv = reinterpret_cast<const float4*>(ws) + (size_t)base * 6;
        const int maxi = (N - base) * 6;      // >= 768 except tail
        #pragma unroll
        for (int i = tid; i < TILE*6; i += TILE) {
            const int ic = (i < maxi) ? i : (maxi - 1);
            float4 v = __ldg(wsv + ic);
            __nv_bfloat162 h0a = __float22bfloat162_rn(make_float2(v.x, v.y));
            __nv_bfloat162 h0b = __float22bfloat162_rn(make_float2(v.z, v.w));
            float2 rlo = make_float2(v.x - __low2float(h0a), v.y - __high2float(h0a));
            float2 rhi = make_float2(v.z - __low2float(h0b), v.w - __high2float(h0b));
            __nv_bfloat162 h1a = __float22bfloat162_rn(rlo);
            __nv_bfloat162 h1b = __float22bfloat162_rn(rhi);

            const unsigned int row  = (unsigned)(i / 6);
            const unsigned int part = (unsigned)(i % 6);
            const unsigned int swz  = (row & 7u) * 16u;
            const unsigned int c0   = (part*8u) ^ swz;
            const unsigned int c1   = (64u + part*8u) ^ swz;
            uint2 u0 = make_uint2(*(unsigned int*)&h0a, *(unsigned int*)&h0b);
            uint2 u1 = make_uint2(*(unsigned int*)&h1a, *(unsigned int*)&h1b);
            *reinterpret_cast<uint2*>(sm + SMA + row*128u + c0) = u0;
            *reinterpret_cast<uint2*>(sm + SMA + row*128u + c1) = u1;
        }
    }

    // ---- copy B frag images (512 words = 128 uint4), frag order ----
    {
        const uint4* src = reinterpret_cast<const uint4*>(g_Bf) + (size_t)blo * 128;
        reinterpret_cast<uint4*>(sm + SMBF)[tid] = __ldg(src + tid);
    }
    __syncthreads();

    // ---- B fragments: coalesced LDS.32, [img][kt][nt][r] ----
    uint32_t bfr[2][2][2][2];
    {
        const uint32_t* Bf = reinterpret_cast<const uint32_t*>(sm + SMBF);
        #pragma unroll
        for (int img = 0; img < 2; img++)
            #pragma unroll
            for (int kt = 0; kt < 2; kt++)
                #pragma unroll
                for (int nt = 0; nt < 2; nt++)
                    #pragma unroll
                    for (int r = 0; r < 2; r++)
                        bfr[img][kt][nt][r] =
                            Bf[((((img*2 + kt)*2 + nt)*2 + r) << 5) + lane];
    }

    // ---- MMA mainloop: 2 m-tiles; A frags reused across the 3 split terms --
    float acc[2][2][4];
    #pragma unroll
    for (int mt = 0; mt < 2; mt++)
        #pragma unroll
        for (int nt = 0; nt < 2; nt++)
            #pragma unroll
            for (int e = 0; e < 4; e++) acc[mt][nt][e] = 0.0f;

    const int rowb = wid * 32;
    #pragma unroll
    for (int mt = 0; mt < 2; mt++) {
        const unsigned int row = (unsigned)(rowb + mt*16 + (lane & 15));
        const unsigned int swz = (row & 7u) * 16u;
        const uint32_t rb = smb + SMA + row*128u;
        const unsigned int kc = (unsigned)(lane >> 4) * 16u;
        uint32_t A0[4], A1[4], C0[4], C1[4];
        ldm_x4(rb + (( 0u + kc) ^ swz), A0[0], A0[1], A0[2], A0[3]);  // w0 k0-15
        ldm_x4(rb + ((32u + kc) ^ swz), A1[0], A1[1], A1[2], A1[3]);  // w0 k16-31
        ldm_x4(rb + ((64u + kc) ^ swz), C0[0], C0[1], C0[2], C0[3]);  // w1 k0-15
        ldm_x4(rb + ((96u + kc) ^ swz), C1[0], C1[1], C1[2], C1[3]);  // w1 k16-31
        #pragma unroll
        for (int nt = 0; nt < 2; nt++) {
            float* c = acc[mt][nt];
            mma_bf16(c, A0, bfr[0][0][nt][0], bfr[0][0][nt][1]);  // w0*a0
            mma_bf16(c, A1, bfr[0][1][nt][0], bfr[0][1][nt][1]);
            mma_bf16(c, A0, bfr[1][0][nt][0], bfr[1][0][nt][1]);  // w0*a1
            mma_bf16(c, A1, bfr[1][1][nt][0], bfr[1][1][nt][1]);
            mma_bf16(c, C0, bfr[0][0][nt][0], bfr[0][0][nt][1]);  // w1*a0
            mma_bf16(c, C1, bfr[0][1][nt][0], bfr[0][1][nt][1]);
        }
    }

    // ---- epilogue: frags -> warp-local smem overlay of own panel rows ----
    __syncwarp();
    {
        char* p = sm + SMA;
        #pragma unroll
        for (int mt = 0; mt < 2; mt++)
            #pragma unroll
            for (int nt = 0; nt < 2; nt++) {
                unsigned int r0 = (unsigned)(rowb + mt*16 + (lane >> 2));
                unsigned int r1 = r0 + 8;
                unsigned int cb = ((unsigned)nt*8u + (unsigned)(lane & 3)*2u) * 4u;
                float2 v0 = make_float2(acc[mt][nt][0], acc[mt][nt][1]);
                float2 v1 = make_float2(acc[mt][nt][2], acc[mt][nt][3]);
                *reinterpret_cast<float2*>(p + (r0*128u + (cb ^ ((r0 & 7u)*16u)))) = v0;
                *reinterpret_cast<float2*>(p + (r1*128u + (cb ^ ((r1 & 7u)*16u)))) = v1;
            }
    }
    __syncwarp();

    float tv[16];
    {
        const char* p = sm + SMA;
        const unsigned int swz = (unsigned)(tid & 7) * 16u;
        #pragma unroll
        for (int c = 0; c < 4; c++) {
            float4 q = *reinterpret_cast<const float4*>(
                p + ((unsigned)tid*128u + (((unsigned)c*16u) ^ swz)));
            tv[c*4+0] = q.x; tv[c*4+1] = q.y; tv[c*4+2] = q.z; tv[c*4+3] = q.w;
        }
    }

    // scalar fixup for points whose batch != blo (rare boundary tiles)
    if (b != blo) {
        const float* Ab = g_A + (size_t)b * 288;
        const float* wp = ws + (size_t)nc * 24;
        float a12[12];
        #pragma unroll
        for (int i = 0; i < 12; i++) a12[i] = 0.0f;
        float sw = 0.0f;
        for (int k = 0; k < 24; k++) {
            float wk = __ldg(wp + k);
            sw += wk;
            #pragma unroll
            for (int i = 0; i < 12; i++) a12[i] += wk * __ldg(Ab + k*12 + i);
        }
        #pragma unroll
        for (int i = 0; i < 12; i++) tv[i] = a12[i];
        tv[12] = 0.0f; tv[13] = 0.0f; tv[14] = 0.0f; tv[15] = sw;
    }

    if (n < N) {
        float4* Tp = reinterpret_cast<float4*>(outT + (size_t)n * 16);
        Tp[0] = make_float4(tv[0],  tv[1],  tv[2],  tv[3]);
        Tp[1] = make_float4(tv[4],  tv[5],  tv[6],  tv[7]);
        Tp[2] = make_float4(tv[8],  tv[9],  tv[10], tv[11]);
        Tp[3] = make_float4(tv[12], tv[13], tv[14], tv[15]);

        outP[(size_t)n*3 + 0] = tv[0]*px + tv[1]*py + tv[2] *pz + tv[3];
        outP[(size_t)n*3 + 1] = tv[4]*px + tv[5]*py + tv[6] *pz + tv[7];
        outP[(size_t)n*3 + 2] = tv[8]*px + tv[9]*py + tv[10]*pz + tv[11];
    }
}

// =============================== launch ====================================
extern "C" void kernel_launch(void* const* d_in, const int* in_sizes, int n_in,
                              void* d_out, int out_size)
{
    const float* ps    = (const float*)d_in[0];
    const float* Js    = (const float*)d_in[1];
    const float* ws    = (const float*)d_in[2];
    const float* poses = (const float*)d_in[3];
    const void*  batch = d_in[4];

    const int N = in_sizes[0] / 3;
    int B = in_sizes[3] / 72;
    if (B > MAX_B) B = MAX_B;

    float* out   = (float*)d_out;
    float* outP  = out;                                  // N*3
    float* outT  = outP + (size_t)N * 3;                 // N*16
    float* outRs = outT + (size_t)N * 16;                // B*216
    float* outJt = outRs + (size_t)B * 216;              // B*72

    rig_kernel<<<B, 32>>>(Js, poses, outRs, outJt);

    const int blocks = (N + TILE - 1) / TILE;
    pts_kernel<<<blocks, TILE>>>(ps, ws, batch, outP, outT, N);
}